// round 8
// baseline (speedup 1.0000x reference)
#include <cuda_runtime.h>
#include <math.h>

// Problem constants
#define BB   8
#define PP   2048
#define DD   1024
#define EE   16
#define SS   64
#define DKK  128
#define HH   16
#define NTOK (BB*PP)          // 16384
#define TOK  16               // tokens per CTA
#define TOKP 18               // padded token row (9 ull)
#define THREADS 512

typedef unsigned long long ull;

__device__ __forceinline__ float sigmoidf_(float v) { return 1.0f / (1.0f + expf(-v)); }

// packed f32x2 helpers (sm_100+)
__device__ __forceinline__ ull pk(float lo, float hi) {
    ull r; asm("mov.b64 %0,{%1,%2};" : "=l"(r) : "f"(lo), "f"(hi)); return r;
}
__device__ __forceinline__ void upk(ull v, float& lo, float& hi) {
    asm("mov.b64 {%0,%1},%2;" : "=f"(lo), "=f"(hi) : "l"(v));
}
__device__ __forceinline__ void ffma2(ull& acc, ull a, ull b) {
    asm("fma.rn.f32x2 %0,%1,%2,%0;" : "+l"(acc) : "l"(a), "l"(b));
}
__device__ __forceinline__ ull add2(ull a, ull b) {
    ull r; asm("add.rn.f32x2 %0,%1,%2;" : "=l"(r) : "l"(a), "l"(b)); return r;
}

// ---- precomputed per-expert constants (device globals: no allocation) ------
__device__ float gC[EE][SS][SS];   // C_e = wv_e @ wout_e   (64x64)
__device__ float gQ[EE][SS];       // q_e = wv_e @ dbar_e   (64)
__device__ float gWE[EE];          // pos_w * beta_w
__device__ float gAW[EE];          // sigmoid(alpha)

// ============================ pre-kernel ====================================
__global__ void precomp_kernel(
    const float* __restrict__ wv,
    const float* __restrict__ wout,
    const float* __restrict__ penta,
    const float* __restrict__ betas,
    const float* __restrict__ alpha,
    const float* __restrict__ pos_embed)
{
    const int e = blockIdx.x >> 2;
    const int q = blockIdx.x & 3;
    const int tid = threadIdx.x;
    const int warp = tid >> 5, lane = tid & 31;

    __shared__ float pinv[5];
    __shared__ float dbar[DKK];

    if (q == 0) {
        if (warp < 5) {
            float4 p = reinterpret_cast<const float4*>(penta + (long)(e * 5 + warp) * DKK)[lane];
            float sq = p.x * p.x + p.y * p.y + p.z * p.z + p.w * p.w;
            #pragma unroll
            for (int o = 16; o; o >>= 1) sq += __shfl_xor_sync(0xffffffffu, sq, o);
            if (lane == 0) pinv[warp] = rsqrtf(sq) * 0.2f;
        }
        if (warp == 6) {
            float4 pv = reinterpret_cast<const float4*>(pos_embed)[e * 32 + lane];
            float s = pv.x + pv.y + pv.z + pv.w;
            #pragma unroll
            for (int o = 16; o; o >>= 1) s += __shfl_xor_sync(0xffffffffu, s, o);
            if (lane == 0) {
                float pos_w = sigmoidf_(s * (1.0f / 128.0f));
                const int offs[4] = {-2, -1, 1, 2};
                float nv = 0.0f, bs = 0.0f;
                #pragma unroll
                for (int j = 0; j < 4; j++) {
                    int nb = e + offs[j];
                    if (nb >= 0 && nb < EE) { nv += 1.0f; bs += sigmoidf_(betas[e * 4 + j]); }
                }
                gWE[e] = pos_w * (1.0f + bs / nv);
                gAW[e] = sigmoidf_(alpha[e]);
            }
        }
        __syncthreads();
        if (tid < DKK) {
            float a = 0.0f;
            #pragma unroll
            for (int v = 0; v < 5; v++)
                a = fmaf(penta[(long)(e * 5 + v) * DKK + tid], pinv[v], a);
            dbar[tid] = a;
        }
        __syncthreads();
        if (tid < SS) {
            const float* wvp = wv + ((long)e * SS + tid) * DKK;
            float a = 0.0f;
            for (int d = 0; d < DKK; d++) a = fmaf(wvp[d], dbar[d], a);
            gQ[e][tid] = a;
        }
    }

    // C_e rows [q*16, q*16+16)
    {
        const int s  = q * 16 + (tid >> 4);
        const int c0 = (tid & 15) * 4;
        float4 acc = make_float4(0.f, 0.f, 0.f, 0.f);
        const float* wvp = wv + ((long)e * SS + s) * DKK;
        const float* wop = wout + (long)e * DKK * SS + c0;
        #pragma unroll 4
        for (int d = 0; d < DKK; d++) {
            float a = wvp[d];
            float4 w = *reinterpret_cast<const float4*>(wop + (long)d * SS);
            acc.x = fmaf(a, w.x, acc.x); acc.y = fmaf(a, w.y, acc.y);
            acc.z = fmaf(a, w.z, acc.z); acc.w = fmaf(a, w.w, acc.w);
        }
        *reinterpret_cast<float4*>(&gC[e][s][c0]) = acc;
    }
}

// ============================ main kernel ===================================
struct __align__(16) Smem {
    float fT[DD][TOKP];         // 73728 B : xn, [channel][token], token pairs 8B-contig
    ull   h2[EE][TOK][9];       // 18432 B : gate hidden, j-pairs, row padded to 9 ull
    float Vdbraw[TOK][EE];      // xn_e . q_e  (pre-gscale)
    float gscale[EE][TOK];
    float mask_s[TOK][EE];
    float mw_s[TOK][EE];
    float den_s[TOK];
    float fused_s[TOK];
};

__global__ __launch_bounds__(THREADS, 2)
void cantor_moe_kernel(
    const float* __restrict__ x,
    const float* __restrict__ fingerprints,
    const float* __restrict__ ln_gamma,
    const float* __restrict__ ln_beta,
    const float* __restrict__ w1,
    const float* __restrict__ b1,
    const float* __restrict__ w2,
    const float* __restrict__ b2,
    const float* __restrict__ temperature,
    float* __restrict__ out)
{
    extern __shared__ unsigned char smem_raw[];
    Smem& sm = *reinterpret_cast<Smem*>(smem_raw);

    const int tid  = threadIdx.x;
    const int warp = tid >> 5;
    const int lane = tid & 31;
    const long g0  = (long)blockIdx.x * TOK;

    // ---------------- LN: warp t -------------------------------------------
    {
        const int t = warp;
        const long g = g0 + t;
        const float* xs = x + g * DD;
        const float4* xr = reinterpret_cast<const float4*>(xs);
        float s = 0.0f, sq = 0.0f;
        #pragma unroll
        for (int i = 0; i < 8; i++) {
            float4 v = xr[i * 32 + lane];
            s  += v.x + v.y + v.z + v.w;
            sq += v.x * v.x + v.y * v.y + v.z * v.z + v.w * v.w;
        }
        #pragma unroll
        for (int o = 16; o; o >>= 1) {
            s  += __shfl_xor_sync(0xffffffffu, s,  o);
            sq += __shfl_xor_sync(0xffffffffu, sq, o);
        }
        float mean = s * (1.0f / DD);
        float rstd = rsqrtf(sq * (1.0f / DD) - mean * mean + 1e-5f);
        // pass 2: scalar channel mapping c = j*32+lane  -> 2-way STS banks
        #pragma unroll 8
        for (int j = 0; j < 32; j++) {
            int c = j * 32 + lane;
            float xv = xs[c];                   // L1/L2 hit
            float gm = ln_gamma[c];
            float bt = ln_beta[c];
            sm.fT[c][t] = (xv - mean) * rstd * gm + bt;
        }
    }
    __syncthreads();   // S1: fT(xn) ready

    // -------- Phase B: tid<256 gate hidden | tid>=256 masks + Vdbraw --------
    if (tid < 256) {
        // thread = (e, jg, tq): 4 tokens (pairs 2tq,2tq+1), 4 j (pairs 2jg,2jg+1)
        const int e  = tid >> 4;
        const int jg = (tid >> 2) & 3;
        const int tq = tid & 3;
        ull acc[4][2];
        #pragma unroll
        for (int t = 0; t < 4; t++) { acc[t][0] = 0ull; acc[t][1] = 0ull; }
        const ull* fb = reinterpret_cast<const ull*>(&sm.fT[e * SS][0]);
        const float* w1b = w1 + (long)e * SS * HH + jg * 4;
        #pragma unroll 4
        for (int s = 0; s < SS; s++) {
            ull f01 = fb[s * 9 + 2 * tq];
            ull f23 = fb[s * 9 + 2 * tq + 1];
            float f0, f1, f2, f3;
            upk(f01, f0, f1); upk(f23, f2, f3);
            ulonglong2 w12 = *reinterpret_cast<const ulonglong2*>(w1b + (long)s * HH);
            ull fd0 = pk(f0, f0), fd1 = pk(f1, f1), fd2 = pk(f2, f2), fd3 = pk(f3, f3);
            ffma2(acc[0][0], fd0, w12.x); ffma2(acc[0][1], fd0, w12.y);
            ffma2(acc[1][0], fd1, w12.x); ffma2(acc[1][1], fd1, w12.y);
            ffma2(acc[2][0], fd2, w12.x); ffma2(acc[2][1], fd2, w12.y);
            ffma2(acc[3][0], fd3, w12.x); ffma2(acc[3][1], fd3, w12.y);
        }
        float2 b1a = *reinterpret_cast<const float2*>(b1 + e * HH + jg * 4);
        float2 b1b = *reinterpret_cast<const float2*>(b1 + e * HH + jg * 4 + 2);
        #pragma unroll
        for (int t = 0; t < 4; t++) {
            const int tok = tq * 4 + t;
            float h0, h1, h2v, h3;
            upk(acc[t][0], h0, h1);
            upk(acc[t][1], h2v, h3);
            h0 += b1a.x; h1 += b1a.y; h2v += b1b.x; h3 += b1b.y;
            h0  = 0.5f * h0  * (1.0f + erff(h0  * 0.70710678118654752f));
            h1  = 0.5f * h1  * (1.0f + erff(h1  * 0.70710678118654752f));
            h2v = 0.5f * h2v * (1.0f + erff(h2v * 0.70710678118654752f));
            h3  = 0.5f * h3  * (1.0f + erff(h3  * 0.70710678118654752f));
            sm.h2[e][tok][2 * jg + 0] = pk(h0, h1);
            sm.h2[e][tok][2 * jg + 1] = pk(h2v, h3);
        }
    } else {
        // masks / mw
        {
            const int qq = tid - 256;
            const int t = qq >> 4, e = qq & 15;
            const long g = g0 + t;
            float f = fingerprints[(int)(g & (PP - 1))];
            float fmin = fmaxf(0.0f, e * (1.0f / EE) - 0.03125f);
            float fmax = fminf(1.0f, (e + 1) * (1.0f / EE) + 0.03125f);
            float mval = (f >= fmin && f < fmax) ? 1.0f : 0.0f;
            sm.mask_s[t][e] = mval;
            sm.mw_s[t][e]   = mval * gWE[e];
        }
        // Vdbraw: warp w (8..15) handles experts w-8 and w
        #pragma unroll
        for (int ee = 0; ee < 2; ee++) {
            const int e = (warp - 8) + ee * 8;
            ull acc[8];
            #pragma unroll
            for (int p = 0; p < 8; p++) acc[p] = 0ull;
            #pragma unroll
            for (int si = 0; si < 2; si++) {
                const int s = lane + si * 32;
                float qv = gQ[e][s];
                ull qd = pk(qv, qv);
                const ull* fp = reinterpret_cast<const ull*>(&sm.fT[e * SS + s][0]);
                #pragma unroll
                for (int p = 0; p < 8; p++) ffma2(acc[p], fp[p], qd);
            }
            #pragma unroll
            for (int o = 16; o; o >>= 1)
                #pragma unroll
                for (int p = 0; p < 8; p++)
                    acc[p] = add2(acc[p], __shfl_xor_sync(0xffffffffu, acc[p], o));
            if (lane == 0) {
                #pragma unroll
                for (int p = 0; p < 8; p++) {
                    float lo, hi; upk(acc[p], lo, hi);
                    sm.Vdbraw[2 * p + 0][e] = lo;
                    sm.Vdbraw[2 * p + 1][e] = hi;
                }
            }
        }
    }
    __syncthreads();   // S2: h2, mask, mw, Vdbraw ready

    // -------- Phase C: gscale (tid<256) + den -------------------------------
    if (tid < TOK * EE) {
        const int e = tid >> 4, t = tid & 15;
        ull acc = 0ull;
        const ull* hp = &sm.h2[e][t][0];
        const ull* w2p = reinterpret_cast<const ull*>(w2 + e * HH);
        #pragma unroll
        for (int jp = 0; jp < 8; jp++) ffma2(acc, hp[jp], w2p[jp]);
        float lo, hi; upk(acc, lo, hi);
        float gate = sigmoidf_(lo + hi + b2[e]);
        float aw = gAW[e];
        sm.gscale[e][t] = gate * aw + (1.0f - aw);
    } else if (tid < TOK * EE + TOK) {
        const int t = tid - TOK * EE;
        float s = 0.0f;
        #pragma unroll
        for (int e = 0; e < EE; e++) s += sm.mw_s[t][e];
        sm.den_s[t] = fmaxf(s, 1e-6f);
    }
    __syncthreads();   // S3

    // -------- Phase D: fused scalar (gscale folded in) ----------------------
    if (tid < TOK) {
        const int t = tid;
        float s = 0.0f;
        #pragma unroll
        for (int e = 0; e < EE; e++)
            s += sm.mw_s[t][e] * sm.gscale[e][t] * sm.Vdbraw[t][e];
        sm.fused_s[t] = s / (sm.den_s[t] * fabsf(temperature[0]));
    }
    __syncthreads();   // S4

    // -------- Phase E: out = x + cscale*(xn_e @ C_e)  warp=e, lane=(tq,cg) --
    {
        const int e  = warp;
        const int tq = lane >> 3;           // token quad (4 tokens)
        const int cg = lane & 7;            // col group (8 cols)
        ull acc[4][4];                      // [token in quad][col pair]
        #pragma unroll
        for (int t = 0; t < 4; t++)
            #pragma unroll
            for (int c = 0; c < 4; c++) acc[t][c] = 0ull;
        const ull* fb = reinterpret_cast<const ull*>(&sm.fT[e * SS][0]);
        const ulonglong2* Cb = reinterpret_cast<const ulonglong2*>(&gC[e][0][cg * 8]);
        #pragma unroll 2
        for (int s = 0; s < SS; s++) {
            ull f01 = fb[s * 9 + 2 * tq];
            ull f23 = fb[s * 9 + 2 * tq + 1];
            ulonglong2 cA = Cb[s * 16];          // cols cg*8 .. +3
            ulonglong2 cB = Cb[s * 16 + 1];      // cols cg*8+4 .. +7
            float f0, f1, f2, f3;
            upk(f01, f0, f1); upk(f23, f2, f3);
            ull fd0 = pk(f0, f0), fd1 = pk(f1, f1), fd2 = pk(f2, f2), fd3 = pk(f3, f3);
            ffma2(acc[0][0], fd0, cA.x); ffma2(acc[0][1], fd0, cA.y);
            ffma2(acc[0][2], fd0, cB.x); ffma2(acc[0][3], fd0, cB.y);
            ffma2(acc[1][0], fd1, cA.x); ffma2(acc[1][1], fd1, cA.y);
            ffma2(acc[1][2], fd1, cB.x); ffma2(acc[1][3], fd1, cB.y);
            ffma2(acc[2][0], fd2, cA.x); ffma2(acc[2][1], fd2, cA.y);
            ffma2(acc[2][2], fd2, cB.x); ffma2(acc[2][3], fd2, cB.y);
            ffma2(acc[3][0], fd3, cA.x); ffma2(acc[3][1], fd3, cA.y);
            ffma2(acc[3][2], fd3, cB.x); ffma2(acc[3][3], fd3, cB.y);
        }
        #pragma unroll
        for (int t = 0; t < 4; t++) {
            const int tok = tq * 4 + t;
            const long g = g0 + tok;
            float cs = sm.fused_s[tok] * sm.mask_s[tok][e] * sm.gscale[e][tok];
            float a0, a1, a2, a3, a4, a5, a6, a7;
            upk(acc[t][0], a0, a1); upk(acc[t][1], a2, a3);
            upk(acc[t][2], a4, a5); upk(acc[t][3], a6, a7);
            const float* xb = x + g * DD + e * SS + cg * 8;
            float* ob = out + g * DD + e * SS + cg * 8;
            float4 xv0 = *reinterpret_cast<const float4*>(xb);
            float4 xv1 = *reinterpret_cast<const float4*>(xb + 4);
            float4 o0, o1;
            o0.x = xv0.x + cs * a0; o0.y = xv0.y + cs * a1;
            o0.z = xv0.z + cs * a2; o0.w = xv0.w + cs * a3;
            o1.x = xv1.x + cs * a4; o1.y = xv1.y + cs * a5;
            o1.z = xv1.z + cs * a6; o1.w = xv1.w + cs * a7;
            *reinterpret_cast<float4*>(ob) = o0;
            *reinterpret_cast<float4*>(ob + 4) = o1;
        }
    }
}

extern "C" void kernel_launch(void* const* d_in, const int* in_sizes, int n_in,
                              void* d_out, int out_size)
{
    (void)in_sizes; (void)n_in; (void)out_size;
    const float* x            = (const float*)d_in[0];
    const float* fingerprints = (const float*)d_in[1];
    const float* ln_gamma     = (const float*)d_in[2];
    const float* ln_beta      = (const float*)d_in[3];
    const float* w1           = (const float*)d_in[4];
    const float* b1           = (const float*)d_in[5];
    const float* w2           = (const float*)d_in[6];
    const float* b2           = (const float*)d_in[7];
    const float* alpha        = (const float*)d_in[8];
    const float* wv           = (const float*)d_in[9];
    const float* penta        = (const float*)d_in[10];
    const float* betas        = (const float*)d_in[11];
    const float* wout         = (const float*)d_in[12];
    const float* pos_embed    = (const float*)d_in[13];
    const float* temperature  = (const float*)d_in[14];
    float* out = (float*)d_out;

    precomp_kernel<<<64, 256>>>(wv, wout, penta, betas, alpha, pos_embed);

    cudaFuncSetAttribute(cantor_moe_kernel,
                         cudaFuncAttributeMaxDynamicSharedMemorySize,
                         (int)sizeof(Smem));

    dim3 grid(NTOK / TOK);
    cantor_moe_kernel<<<grid, THREADS, sizeof(Smem)>>>(
        x, fingerprints, ln_gamma, ln_beta, w1, b1, w2, b2,
        temperature, out);
}

// round 9
// speedup vs baseline: 1.1527x; 1.1527x over previous
#include <cuda_runtime.h>
#include <math.h>

// Problem constants
#define BB   8
#define PP   2048
#define DD   1024
#define EE   16
#define SS   64
#define DKK  128
#define HH   16
#define NTOK (BB*PP)          // 16384
#define TOK  16               // tokens per CTA
#define TOKP 20               // padded row: 80B -> token pairs 16B aligned
#define THREADS 512

typedef unsigned long long ull;

__device__ __forceinline__ float sigmoidf_(float v) { return 1.0f / (1.0f + expf(-v)); }

// packed f32x2 helpers (sm_100+)
__device__ __forceinline__ ull pk(float lo, float hi) {
    ull r; asm("mov.b64 %0,{%1,%2};" : "=l"(r) : "f"(lo), "f"(hi)); return r;
}
__device__ __forceinline__ void upk(ull v, float& lo, float& hi) {
    asm("mov.b64 {%0,%1},%2;" : "=f"(lo), "=f"(hi) : "l"(v));
}
__device__ __forceinline__ void ffma2(ull& acc, ull a, ull b) {
    asm("fma.rn.f32x2 %0,%1,%2,%0;" : "+l"(acc) : "l"(a), "l"(b));
}
__device__ __forceinline__ ull add2(ull a, ull b) {
    ull r; asm("add.rn.f32x2 %0,%1,%2;" : "=l"(r) : "l"(a), "l"(b)); return r;
}

// ---- precomputed per-expert constants (device globals: no allocation) ------
__device__ __align__(16) float gC[EE][SS][SS];   // C_e = wv_e @ wout_e (64x64)
__device__ __align__(16) float gQ[EE][SS];       // q_e = wv_e @ dbar_e
__device__ float gWE[EE];          // pos_w * beta_w
__device__ float gAW[EE];          // sigmoid(alpha)

// ============================ pre-kernel ====================================
__global__ void precomp_kernel(
    const float* __restrict__ wv,
    const float* __restrict__ wout,
    const float* __restrict__ penta,
    const float* __restrict__ betas,
    const float* __restrict__ alpha,
    const float* __restrict__ pos_embed)
{
    const int e = blockIdx.x >> 2;
    const int q = blockIdx.x & 3;
    const int tid = threadIdx.x;
    const int warp = tid >> 5, lane = tid & 31;

    __shared__ float pinv[5];
    __shared__ float dbar[DKK];

    if (q == 0) {
        if (warp < 5) {
            float4 p = reinterpret_cast<const float4*>(penta + (long)(e * 5 + warp) * DKK)[lane];
            float sq = p.x * p.x + p.y * p.y + p.z * p.z + p.w * p.w;
            #pragma unroll
            for (int o = 16; o; o >>= 1) sq += __shfl_xor_sync(0xffffffffu, sq, o);
            if (lane == 0) pinv[warp] = rsqrtf(sq) * 0.2f;
        }
        if (warp == 6) {
            float4 pv = reinterpret_cast<const float4*>(pos_embed)[e * 32 + lane];
            float s = pv.x + pv.y + pv.z + pv.w;
            #pragma unroll
            for (int o = 16; o; o >>= 1) s += __shfl_xor_sync(0xffffffffu, s, o);
            if (lane == 0) {
                float pos_w = sigmoidf_(s * (1.0f / 128.0f));
                const int offs[4] = {-2, -1, 1, 2};
                float nv = 0.0f, bs = 0.0f;
                #pragma unroll
                for (int j = 0; j < 4; j++) {
                    int nb = e + offs[j];
                    if (nb >= 0 && nb < EE) { nv += 1.0f; bs += sigmoidf_(betas[e * 4 + j]); }
                }
                gWE[e] = pos_w * (1.0f + bs / nv);
                gAW[e] = sigmoidf_(alpha[e]);
            }
        }
        __syncthreads();
        if (tid < DKK) {
            float a = 0.0f;
            #pragma unroll
            for (int v = 0; v < 5; v++)
                a = fmaf(penta[(long)(e * 5 + v) * DKK + tid], pinv[v], a);
            dbar[tid] = a;
        }
        __syncthreads();
        if (tid < SS) {
            const float* wvp = wv + ((long)e * SS + tid) * DKK;
            float a = 0.0f;
            for (int d = 0; d < DKK; d++) a = fmaf(wvp[d], dbar[d], a);
            gQ[e][tid] = a;
        }
    }

    // C_e rows [q*16, q*16+16)
    {
        const int s  = q * 16 + (tid >> 4);
        const int c0 = (tid & 15) * 4;
        float4 acc = make_float4(0.f, 0.f, 0.f, 0.f);
        const float* wvp = wv + ((long)e * SS + s) * DKK;
        const float* wop = wout + (long)e * DKK * SS + c0;
        #pragma unroll 4
        for (int d = 0; d < DKK; d++) {
            float a = wvp[d];
            float4 w = *reinterpret_cast<const float4*>(wop + (long)d * SS);
            acc.x = fmaf(a, w.x, acc.x); acc.y = fmaf(a, w.y, acc.y);
            acc.z = fmaf(a, w.z, acc.z); acc.w = fmaf(a, w.w, acc.w);
        }
        *reinterpret_cast<float4*>(&gC[e][s][c0]) = acc;
    }
}

// ============================ main kernel ===================================
struct __align__(16) Smem {
    float fT[DD][TOKP];         // 81920 B : xn, [channel][token], pairs 16B-aligned
    ull   h2[EE][TOK][9];       // 18432 B : gate hidden, j-pairs, row padded to 9 ull
    float Vdbraw[TOK][EE];      // xn_e . q_e  (pre-gscale)
    float gscale[EE][TOK];
    float mask_s[TOK][EE];
    float mw_s[TOK][EE];
    float den_s[TOK];
    float fused_s[TOK];
    float mean_s[TOK];
    float rstd_s[TOK];
};

__global__ __launch_bounds__(THREADS, 2)
void cantor_moe_kernel(
    const float* __restrict__ x,
    const float* __restrict__ fingerprints,
    const float* __restrict__ ln_gamma,
    const float* __restrict__ ln_beta,
    const float* __restrict__ w1,
    const float* __restrict__ b1,
    const float* __restrict__ w2,
    const float* __restrict__ b2,
    const float* __restrict__ temperature,
    float* __restrict__ out)
{
    extern __shared__ unsigned char smem_raw[];
    Smem& sm = *reinterpret_cast<Smem*>(smem_raw);

    const int tid  = threadIdx.x;
    const int warp = tid >> 5;
    const int lane = tid & 31;
    const long g0  = (long)blockIdx.x * TOK;

    // ---------------- LN pass 1: stats (warp t, vectorized) -----------------
    {
        const int t = warp;
        const long g = g0 + t;
        const float4* xr = reinterpret_cast<const float4*>(x + g * DD);
        float s = 0.0f, sq = 0.0f;
        #pragma unroll
        for (int i = 0; i < 8; i++) {
            float4 v = xr[i * 32 + lane];
            s  += v.x + v.y + v.z + v.w;
            sq += v.x * v.x + v.y * v.y + v.z * v.z + v.w * v.w;
        }
        #pragma unroll
        for (int o = 16; o; o >>= 1) {
            s  += __shfl_xor_sync(0xffffffffu, s,  o);
            sq += __shfl_xor_sync(0xffffffffu, sq, o);
        }
        if (lane == 0) {
            float mean = s * (1.0f / DD);
            sm.mean_s[t] = mean;
            sm.rstd_s[t] = rsqrtf(sq * (1.0f / DD) - mean * mean + 1e-5f);
        }
    }
    __syncthreads();   // S0: stats ready

    // ---------------- LN pass 2: transpose store, STS.128 -------------------
    // task = (cb 0..31, tq 0..3); c = cb*32+lane; thread writes 4 tokens of c
    {
        #pragma unroll
        for (int it = 0; it < 8; it++) {
            const int task = it * 16 + warp;
            const int cb = task >> 2, tq = task & 3;
            const int c = cb * 32 + lane;
            const float gm = ln_gamma[c];
            const float bt = ln_beta[c];
            float4 o;
            {
                const int t0 = tq * 4;
                float m0 = sm.mean_s[t0 + 0], r0 = sm.rstd_s[t0 + 0];
                float m1 = sm.mean_s[t0 + 1], r1 = sm.rstd_s[t0 + 1];
                float m2 = sm.mean_s[t0 + 2], r2 = sm.rstd_s[t0 + 2];
                float m3 = sm.mean_s[t0 + 3], r3 = sm.rstd_s[t0 + 3];
                float x0 = x[(g0 + t0 + 0) * DD + c];
                float x1 = x[(g0 + t0 + 1) * DD + c];
                float x2 = x[(g0 + t0 + 2) * DD + c];
                float x3 = x[(g0 + t0 + 3) * DD + c];
                o.x = (x0 - m0) * r0 * gm + bt;
                o.y = (x1 - m1) * r1 * gm + bt;
                o.z = (x2 - m2) * r2 * gm + bt;
                o.w = (x3 - m3) * r3 * gm + bt;
            }
            *reinterpret_cast<float4*>(&sm.fT[c][tq * 4]) = o;
        }
    }
    __syncthreads();   // S1: fT(xn) ready

    // -------- Phase B: tid<256 gate hidden | tid>=256 masks + Vdbraw --------
    if (tid < 256) {
        // thread = (e, jg, tq): 4 tokens (pairs 2tq,2tq+1), 4 j (pairs 2jg,2jg+1)
        const int e  = tid >> 4;
        const int jg = (tid >> 2) & 3;
        const int tq = tid & 3;
        ull acc[4][2];
        #pragma unroll
        for (int t = 0; t < 4; t++) { acc[t][0] = 0ull; acc[t][1] = 0ull; }
        const ulonglong2* f2 = reinterpret_cast<const ulonglong2*>(&sm.fT[e * SS][0]);
        const float* w1b = w1 + (long)e * SS * HH + jg * 4;
        #pragma unroll 4
        for (int s = 0; s < SS; s++) {
            ulonglong2 fq = f2[s * 5 + tq];              // tokens 4tq..4tq+3
            float f0, f1, f2v, f3;
            upk(fq.x, f0, f1); upk(fq.y, f2v, f3);
            ulonglong2 w12 = *reinterpret_cast<const ulonglong2*>(w1b + (long)s * HH);
            ull fd0 = pk(f0, f0), fd1 = pk(f1, f1), fd2 = pk(f2v, f2v), fd3 = pk(f3, f3);
            ffma2(acc[0][0], fd0, w12.x); ffma2(acc[0][1], fd0, w12.y);
            ffma2(acc[1][0], fd1, w12.x); ffma2(acc[1][1], fd1, w12.y);
            ffma2(acc[2][0], fd2, w12.x); ffma2(acc[2][1], fd2, w12.y);
            ffma2(acc[3][0], fd3, w12.x); ffma2(acc[3][1], fd3, w12.y);
        }
        float2 b1a = *reinterpret_cast<const float2*>(b1 + e * HH + jg * 4);
        float2 b1b = *reinterpret_cast<const float2*>(b1 + e * HH + jg * 4 + 2);
        #pragma unroll
        for (int t = 0; t < 4; t++) {
            const int tok = tq * 4 + t;
            float h0, h1, h2v, h3;
            upk(acc[t][0], h0, h1);
            upk(acc[t][1], h2v, h3);
            h0 += b1a.x; h1 += b1a.y; h2v += b1b.x; h3 += b1b.y;
            h0  = 0.5f * h0  * (1.0f + erff(h0  * 0.70710678118654752f));
            h1  = 0.5f * h1  * (1.0f + erff(h1  * 0.70710678118654752f));
            h2v = 0.5f * h2v * (1.0f + erff(h2v * 0.70710678118654752f));
            h3  = 0.5f * h3  * (1.0f + erff(h3  * 0.70710678118654752f));
            sm.h2[e][tok][2 * jg + 0] = pk(h0, h1);
            sm.h2[e][tok][2 * jg + 1] = pk(h2v, h3);
        }
    } else {
        // masks / mw
        {
            const int qq = tid - 256;
            const int t = qq >> 4, e = qq & 15;
            const long g = g0 + t;
            float f = fingerprints[(int)(g & (PP - 1))];
            float fmin = fmaxf(0.0f, e * (1.0f / EE) - 0.03125f);
            float fmax = fminf(1.0f, (e + 1) * (1.0f / EE) + 0.03125f);
            float mval = (f >= fmin && f < fmax) ? 1.0f : 0.0f;
            sm.mask_s[t][e] = mval;
            sm.mw_s[t][e]   = mval * gWE[e];
        }
        // Vdbraw: warp w (8..15) handles experts w-8 and w
        #pragma unroll
        for (int ee = 0; ee < 2; ee++) {
            const int e = (warp - 8) + ee * 8;
            ull acc[8];
            #pragma unroll
            for (int p = 0; p < 8; p++) acc[p] = 0ull;
            #pragma unroll
            for (int si = 0; si < 2; si++) {
                const int s = lane + si * 32;
                float qv = gQ[e][s];
                ull qd = pk(qv, qv);
                const ull* fp = reinterpret_cast<const ull*>(&sm.fT[e * SS + s][0]);
                #pragma unroll
                for (int p = 0; p < 8; p++) ffma2(acc[p], fp[p], qd);
            }
            #pragma unroll
            for (int o = 16; o; o >>= 1)
                #pragma unroll
                for (int p = 0; p < 8; p++)
                    acc[p] = add2(acc[p], __shfl_xor_sync(0xffffffffu, acc[p], o));
            if (lane == 0) {
                #pragma unroll
                for (int p = 0; p < 8; p++) {
                    float lo, hi; upk(acc[p], lo, hi);
                    sm.Vdbraw[2 * p + 0][e] = lo;
                    sm.Vdbraw[2 * p + 1][e] = hi;
                }
            }
        }
    }
    __syncthreads();   // S2: h2, mask, mw, Vdbraw ready

    // -------- Phase C: gscale (tid<256) + den -------------------------------
    if (tid < TOK * EE) {
        const int e = tid >> 4, t = tid & 15;
        ull acc = 0ull;
        const ull* hp = &sm.h2[e][t][0];
        const ull* w2p = reinterpret_cast<const ull*>(w2 + e * HH);
        #pragma unroll
        for (int jp = 0; jp < 8; jp++) ffma2(acc, hp[jp], w2p[jp]);
        float lo, hi; upk(acc, lo, hi);
        float gate = sigmoidf_(lo + hi + b2[e]);
        float aw = gAW[e];
        sm.gscale[e][t] = gate * aw + (1.0f - aw);
    } else if (tid < TOK * EE + TOK) {
        const int t = tid - TOK * EE;
        float s = 0.0f;
        #pragma unroll
        for (int e = 0; e < EE; e++) s += sm.mw_s[t][e];
        sm.den_s[t] = fmaxf(s, 1e-6f);
    }
    __syncthreads();   // S3

    // -------- Phase D: fused scalar (gscale folded in) ----------------------
    if (tid < TOK) {
        const int t = tid;
        float s = 0.0f;
        #pragma unroll
        for (int e = 0; e < EE; e++)
            s += sm.mw_s[t][e] * sm.gscale[e][t] * sm.Vdbraw[t][e];
        sm.fused_s[t] = s / (sm.den_s[t] * fabsf(temperature[0]));
    }
    __syncthreads();   // S4

    // -------- Phase E: out = x + cscale * (xn_e @ C_e)  (warp e) ------------
    {
        const int e = warp;
        ull acc[8][2];                       // [token-pair][col 2lane / 2lane+1]
        #pragma unroll
        for (int p = 0; p < 8; p++) { acc[p][0] = 0ull; acc[p][1] = 0ull; }
        const float* Cb = &gC[e][0][2 * lane];
        const ulonglong2* f2 = reinterpret_cast<const ulonglong2*>(&sm.fT[e * SS][0]);
        #pragma unroll 2
        for (int s = 0; s < SS; s++) {
            float2 cw = *reinterpret_cast<const float2*>(Cb + (long)s * SS);
            ull c0 = pk(cw.x, cw.x), c1 = pk(cw.y, cw.y);
            ulonglong2 fA = f2[s * 5 + 0];   // tokens 0..3
            ulonglong2 fB = f2[s * 5 + 1];   // tokens 4..7
            ulonglong2 fC = f2[s * 5 + 2];   // tokens 8..11
            ulonglong2 fD = f2[s * 5 + 3];   // tokens 12..15
            ffma2(acc[0][0], fA.x, c0); ffma2(acc[0][1], fA.x, c1);
            ffma2(acc[1][0], fA.y, c0); ffma2(acc[1][1], fA.y, c1);
            ffma2(acc[2][0], fB.x, c0); ffma2(acc[2][1], fB.x, c1);
            ffma2(acc[3][0], fB.y, c0); ffma2(acc[3][1], fB.y, c1);
            ffma2(acc[4][0], fC.x, c0); ffma2(acc[4][1], fC.x, c1);
            ffma2(acc[5][0], fC.y, c0); ffma2(acc[5][1], fC.y, c1);
            ffma2(acc[6][0], fD.x, c0); ffma2(acc[6][1], fD.x, c1);
            ffma2(acc[7][0], fD.y, c0); ffma2(acc[7][1], fD.y, c1);
        }
        const float* xb = x + g0 * DD + e * SS + 2 * lane;
        float* ob = out + g0 * DD + e * SS + 2 * lane;
        #pragma unroll
        for (int p = 0; p < 8; p++) {
            float a0lo, a0hi, a1lo, a1hi;
            upk(acc[p][0], a0lo, a0hi);
            upk(acc[p][1], a1lo, a1hi);
            const int t0 = 2 * p, t1 = 2 * p + 1;
            float cs0 = sm.fused_s[t0] * sm.mask_s[t0][e] * sm.gscale[e][t0];
            float cs1 = sm.fused_s[t1] * sm.mask_s[t1][e] * sm.gscale[e][t1];
            float2 xv0 = *reinterpret_cast<const float2*>(xb + (long)t0 * DD);
            float2 xv1 = *reinterpret_cast<const float2*>(xb + (long)t1 * DD);
            float2 o0, o1;
            o0.x = xv0.x + cs0 * a0lo; o0.y = xv0.y + cs0 * a1lo;
            o1.x = xv1.x + cs1 * a0hi; o1.y = xv1.y + cs1 * a1hi;
            *reinterpret_cast<float2*>(ob + (long)t0 * DD) = o0;
            *reinterpret_cast<float2*>(ob + (long)t1 * DD) = o1;
        }
    }
}

extern "C" void kernel_launch(void* const* d_in, const int* in_sizes, int n_in,
                              void* d_out, int out_size)
{
    (void)in_sizes; (void)n_in; (void)out_size;
    const float* x            = (const float*)d_in[0];
    const float* fingerprints = (const float*)d_in[1];
    const float* ln_gamma     = (const float*)d_in[2];
    const float* ln_beta      = (const float*)d_in[3];
    const float* w1           = (const float*)d_in[4];
    const float* b1           = (const float*)d_in[5];
    const float* w2           = (const float*)d_in[6];
    const float* b2           = (const float*)d_in[7];
    const float* alpha        = (const float*)d_in[8];
    const float* wv           = (const float*)d_in[9];
    const float* penta        = (const float*)d_in[10];
    const float* betas        = (const float*)d_in[11];
    const float* wout         = (const float*)d_in[12];
    const float* pos_embed    = (const float*)d_in[13];
    const float* temperature  = (const float*)d_in[14];
    float* out = (float*)d_out;

    precomp_kernel<<<64, 256>>>(wv, wout, penta, betas, alpha, pos_embed);

    cudaFuncSetAttribute(cantor_moe_kernel,
                         cudaFuncAttributeMaxDynamicSharedMemorySize,
                         (int)sizeof(Smem));

    dim3 grid(NTOK / TOK);
    cantor_moe_kernel<<<grid, THREADS, sizeof(Smem)>>>(
        x, fingerprints, ln_gamma, ln_beta, w1, b1, w2, b2,
        temperature, out);
}

// round 10
// speedup vs baseline: 1.2388x; 1.0747x over previous
#include <cuda_runtime.h>
#include <math.h>

// Problem constants
#define BB   8
#define PP   2048
#define DD   1024
#define EE   16
#define SS   64
#define DKK  128
#define HH   16
#define NTOK (BB*PP)          // 16384
#define TOK  16               // tokens per CTA
#define TOKP 20               // padded row: 80B -> token pairs 16B aligned
#define THREADS 512

typedef unsigned long long ull;

__device__ __forceinline__ float sigmoidf_(float v) { return 1.0f / (1.0f + expf(-v)); }

// packed f32x2 helpers (sm_100+)
__device__ __forceinline__ ull pk(float lo, float hi) {
    ull r; asm("mov.b64 %0,{%1,%2};" : "=l"(r) : "f"(lo), "f"(hi)); return r;
}
__device__ __forceinline__ void upk(ull v, float& lo, float& hi) {
    asm("mov.b64 {%0,%1},%2;" : "=f"(lo), "=f"(hi) : "l"(v));
}
__device__ __forceinline__ void ffma2(ull& acc, ull a, ull b) {
    asm("fma.rn.f32x2 %0,%1,%2,%0;" : "+l"(acc) : "l"(a), "l"(b));
}
__device__ __forceinline__ ull add2(ull a, ull b) {
    ull r; asm("add.rn.f32x2 %0,%1,%2;" : "=l"(r) : "l"(a), "l"(b)); return r;
}

// ---- precomputed per-expert constants (device globals: no allocation) ------
__device__ __align__(16) float gC[EE][SS][SS];   // C_e = wv_e @ wout_e (64x64)
__device__ __align__(16) float gQ[EE][SS];       // q_e = wv_e @ dbar_e
__device__ float gWE[EE];          // pos_w * beta_w
__device__ float gAW[EE];          // sigmoid(alpha)

// ==================== pre-kernel 1: per-expert scalars ======================
// grid = 16 (one CTA per expert), 256 threads
__global__ void precomp_scalars_kernel(
    const float* __restrict__ wv,
    const float* __restrict__ penta,
    const float* __restrict__ betas,
    const float* __restrict__ alpha,
    const float* __restrict__ pos_embed)
{
    const int e = blockIdx.x;
    const int tid = threadIdx.x;
    const int warp = tid >> 5, lane = tid & 31;

    __shared__ float pinv[5];
    __shared__ float dbar[DKK];

    if (warp < 5) {
        float4 p = reinterpret_cast<const float4*>(penta + (long)(e * 5 + warp) * DKK)[lane];
        float sq = p.x * p.x + p.y * p.y + p.z * p.z + p.w * p.w;
        #pragma unroll
        for (int o = 16; o; o >>= 1) sq += __shfl_xor_sync(0xffffffffu, sq, o);
        if (lane == 0) pinv[warp] = rsqrtf(sq) * 0.2f;
    }
    if (warp == 6) {
        float4 pv = reinterpret_cast<const float4*>(pos_embed)[e * 32 + lane];
        float s = pv.x + pv.y + pv.z + pv.w;
        #pragma unroll
        for (int o = 16; o; o >>= 1) s += __shfl_xor_sync(0xffffffffu, s, o);
        if (lane == 0) {
            float pos_w = sigmoidf_(s * (1.0f / 128.0f));
            const int offs[4] = {-2, -1, 1, 2};
            float nv = 0.0f, bs = 0.0f;
            #pragma unroll
            for (int j = 0; j < 4; j++) {
                int nb = e + offs[j];
                if (nb >= 0 && nb < EE) { nv += 1.0f; bs += sigmoidf_(betas[e * 4 + j]); }
            }
            gWE[e] = pos_w * (1.0f + bs / nv);
            gAW[e] = sigmoidf_(alpha[e]);
        }
    }
    __syncthreads();
    if (tid < DKK) {
        float a = 0.0f;
        #pragma unroll
        for (int v = 0; v < 5; v++)
            a = fmaf(penta[(long)(e * 5 + v) * DKK + tid], pinv[v], a);
        dbar[tid] = a;
    }
    __syncthreads();
    // gQ: 4 warps, warp handles 16 s-rows, full-warp dot per row via shuffle?
    // simpler: 64 threads, each a full 128-dot with unroll (L1-resident dbar/wv)
    if (tid < SS) {
        const float* wvp = wv + ((long)e * SS + tid) * DKK;
        float a = 0.0f;
        #pragma unroll 8
        for (int d = 0; d < DKK; d++) a = fmaf(wvp[d], dbar[d], a);
        gQ[e][tid] = a;
    }
}

// ==================== pre-kernel 2: C = wv @ wout ===========================
// grid = EE*16 = 256 CTAs, 256 threads; thread -> one C element
__global__ void precomp_C_kernel(
    const float* __restrict__ wv,
    const float* __restrict__ wout)
{
    const int e = blockIdx.x >> 4;
    const int g = blockIdx.x & 15;
    const int s = g * 4 + (threadIdx.x >> 6);   // 4 rows per CTA
    const int c = threadIdx.x & 63;             // col (warp-coalesced)
    const float* wvp = wv + ((long)e * SS + s) * DKK;
    const float* wop = wout + (long)e * DKK * SS + c;
    float acc = 0.0f;
    #pragma unroll 8
    for (int d = 0; d < DKK; d++)
        acc = fmaf(wvp[d], wop[(long)d * SS], acc);
    gC[e][s][c] = acc;
}

// ============================ main kernel ===================================
struct __align__(16) Smem {
    float fT[DD][TOKP];         // 81920 B : xn, [channel][token], pairs 16B-aligned
    ull   h2[EE][TOK][9];       // 18432 B : gate hidden, j-pairs, row padded to 9 ull
    float Vdbraw[TOK][EE];      // xn_e . q_e  (pre-gscale)
    float gscale[EE][TOK];
    float mask_s[TOK][EE];
    float mw_s[TOK][EE];
    float den_s[TOK];
    float fused_s[TOK];
    float mean_s[TOK];
    float rstd_s[TOK];
};

__global__ __launch_bounds__(THREADS, 2)
void cantor_moe_kernel(
    const float* __restrict__ x,
    const float* __restrict__ fingerprints,
    const float* __restrict__ ln_gamma,
    const float* __restrict__ ln_beta,
    const float* __restrict__ w1,
    const float* __restrict__ b1,
    const float* __restrict__ w2,
    const float* __restrict__ b2,
    const float* __restrict__ temperature,
    float* __restrict__ out)
{
    extern __shared__ unsigned char smem_raw[];
    Smem& sm = *reinterpret_cast<Smem*>(smem_raw);

    const int tid  = threadIdx.x;
    const int warp = tid >> 5;
    const int lane = tid & 31;
    const long g0  = (long)blockIdx.x * TOK;

    // ---------------- LN pass 1: stats (warp t, vectorized) -----------------
    {
        const int t = warp;
        const long g = g0 + t;
        const float4* xr = reinterpret_cast<const float4*>(x + g * DD);
        float s = 0.0f, sq = 0.0f;
        #pragma unroll
        for (int i = 0; i < 8; i++) {
            float4 v = xr[i * 32 + lane];
            s  += v.x + v.y + v.z + v.w;
            sq += v.x * v.x + v.y * v.y + v.z * v.z + v.w * v.w;
        }
        #pragma unroll
        for (int o = 16; o; o >>= 1) {
            s  += __shfl_xor_sync(0xffffffffu, s,  o);
            sq += __shfl_xor_sync(0xffffffffu, sq, o);
        }
        if (lane == 0) {
            float mean = s * (1.0f / DD);
            sm.mean_s[t] = mean;
            sm.rstd_s[t] = rsqrtf(sq * (1.0f / DD) - mean * mean + 1e-5f);
        }
    }
    __syncthreads();   // S0: stats ready

    // ---------------- LN pass 2: transpose store, STS.128 -------------------
    {
        #pragma unroll
        for (int it = 0; it < 8; it++) {
            const int task = it * 16 + warp;
            const int cb = task >> 2, tq = task & 3;
            const int c = cb * 32 + lane;
            const float gm = ln_gamma[c];
            const float bt = ln_beta[c];
            float4 o;
            {
                const int t0 = tq * 4;
                float m0 = sm.mean_s[t0 + 0], r0 = sm.rstd_s[t0 + 0];
                float m1 = sm.mean_s[t0 + 1], r1 = sm.rstd_s[t0 + 1];
                float m2 = sm.mean_s[t0 + 2], r2 = sm.rstd_s[t0 + 2];
                float m3 = sm.mean_s[t0 + 3], r3 = sm.rstd_s[t0 + 3];
                float x0 = x[(g0 + t0 + 0) * DD + c];
                float x1 = x[(g0 + t0 + 1) * DD + c];
                float x2 = x[(g0 + t0 + 2) * DD + c];
                float x3 = x[(g0 + t0 + 3) * DD + c];
                o.x = (x0 - m0) * r0 * gm + bt;
                o.y = (x1 - m1) * r1 * gm + bt;
                o.z = (x2 - m2) * r2 * gm + bt;
                o.w = (x3 - m3) * r3 * gm + bt;
            }
            *reinterpret_cast<float4*>(&sm.fT[c][tq * 4]) = o;
        }
    }
    __syncthreads();   // S1: fT(xn) ready

    // -------- Phase B: tid<256 gate hidden | tid>=256 masks + Vdbraw --------
    if (tid < 256) {
        const int e  = tid >> 4;
        const int jg = (tid >> 2) & 3;
        const int tq = tid & 3;
        ull acc[4][2];
        #pragma unroll
        for (int t = 0; t < 4; t++) { acc[t][0] = 0ull; acc[t][1] = 0ull; }
        const ulonglong2* f2 = reinterpret_cast<const ulonglong2*>(&sm.fT[e * SS][0]);
        const float* w1b = w1 + (long)e * SS * HH + jg * 4;
        #pragma unroll 4
        for (int s = 0; s < SS; s++) {
            ulonglong2 fq = f2[s * 5 + tq];              // tokens 4tq..4tq+3
            float f0, f1, f2v, f3;
            upk(fq.x, f0, f1); upk(fq.y, f2v, f3);
            ulonglong2 w12 = *reinterpret_cast<const ulonglong2*>(w1b + (long)s * HH);
            ull fd0 = pk(f0, f0), fd1 = pk(f1, f1), fd2 = pk(f2v, f2v), fd3 = pk(f3, f3);
            ffma2(acc[0][0], fd0, w12.x); ffma2(acc[0][1], fd0, w12.y);
            ffma2(acc[1][0], fd1, w12.x); ffma2(acc[1][1], fd1, w12.y);
            ffma2(acc[2][0], fd2, w12.x); ffma2(acc[2][1], fd2, w12.y);
            ffma2(acc[3][0], fd3, w12.x); ffma2(acc[3][1], fd3, w12.y);
        }
        float2 b1a = *reinterpret_cast<const float2*>(b1 + e * HH + jg * 4);
        float2 b1b = *reinterpret_cast<const float2*>(b1 + e * HH + jg * 4 + 2);
        #pragma unroll
        for (int t = 0; t < 4; t++) {
            const int tok = tq * 4 + t;
            float h0, h1, h2v, h3;
            upk(acc[t][0], h0, h1);
            upk(acc[t][1], h2v, h3);
            h0 += b1a.x; h1 += b1a.y; h2v += b1b.x; h3 += b1b.y;
            h0  = 0.5f * h0  * (1.0f + erff(h0  * 0.70710678118654752f));
            h1  = 0.5f * h1  * (1.0f + erff(h1  * 0.70710678118654752f));
            h2v = 0.5f * h2v * (1.0f + erff(h2v * 0.70710678118654752f));
            h3  = 0.5f * h3  * (1.0f + erff(h3  * 0.70710678118654752f));
            sm.h2[e][tok][2 * jg + 0] = pk(h0, h1);
            sm.h2[e][tok][2 * jg + 1] = pk(h2v, h3);
        }
    } else {
        // masks / mw
        {
            const int qq = tid - 256;
            const int t = qq >> 4, e = qq & 15;
            const long g = g0 + t;
            float f = fingerprints[(int)(g & (PP - 1))];
            float fmin = fmaxf(0.0f, e * (1.0f / EE) - 0.03125f);
            float fmax = fminf(1.0f, (e + 1) * (1.0f / EE) + 0.03125f);
            float mval = (f >= fmin && f < fmax) ? 1.0f : 0.0f;
            sm.mask_s[t][e] = mval;
            sm.mw_s[t][e]   = mval * gWE[e];
        }
        // Vdbraw: warp w (8..15) handles experts w-8 and w
        #pragma unroll
        for (int ee = 0; ee < 2; ee++) {
            const int e = (warp - 8) + ee * 8;
            ull acc[8];
            #pragma unroll
            for (int p = 0; p < 8; p++) acc[p] = 0ull;
            #pragma unroll
            for (int si = 0; si < 2; si++) {
                const int s = lane + si * 32;
                float qv = gQ[e][s];
                ull qd = pk(qv, qv);
                const ull* fp = reinterpret_cast<const ull*>(&sm.fT[e * SS + s][0]);
                #pragma unroll
                for (int p = 0; p < 8; p++) ffma2(acc[p], fp[p], qd);
            }
            #pragma unroll
            for (int o = 16; o; o >>= 1)
                #pragma unroll
                for (int p = 0; p < 8; p++)
                    acc[p] = add2(acc[p], __shfl_xor_sync(0xffffffffu, acc[p], o));
            if (lane == 0) {
                #pragma unroll
                for (int p = 0; p < 8; p++) {
                    float lo, hi; upk(acc[p], lo, hi);
                    sm.Vdbraw[2 * p + 0][e] = lo;
                    sm.Vdbraw[2 * p + 1][e] = hi;
                }
            }
        }
    }
    __syncthreads();   // S2: h2, mask, mw, Vdbraw ready

    // -------- Phase C: gscale (tid<256) + den -------------------------------
    if (tid < TOK * EE) {
        const int e = tid >> 4, t = tid & 15;
        ull acc = 0ull;
        const ull* hp = &sm.h2[e][t][0];
        const ull* w2p = reinterpret_cast<const ull*>(w2 + e * HH);
        #pragma unroll
        for (int jp = 0; jp < 8; jp++) ffma2(acc, hp[jp], w2p[jp]);
        float lo, hi; upk(acc, lo, hi);
        float gate = sigmoidf_(lo + hi + b2[e]);
        float aw = gAW[e];
        sm.gscale[e][t] = gate * aw + (1.0f - aw);
    } else if (tid < TOK * EE + TOK) {
        const int t = tid - TOK * EE;
        float s = 0.0f;
        #pragma unroll
        for (int e = 0; e < EE; e++) s += sm.mw_s[t][e];
        sm.den_s[t] = fmaxf(s, 1e-6f);
    }
    __syncthreads();   // S3

    // -------- Phase D: fused scalar (gscale folded in) ----------------------
    if (tid < TOK) {
        const int t = tid;
        float s = 0.0f;
        #pragma unroll
        for (int e = 0; e < EE; e++)
            s += sm.mw_s[t][e] * sm.gscale[e][t] * sm.Vdbraw[t][e];
        sm.fused_s[t] = s / (sm.den_s[t] * fabsf(temperature[0]));
    }
    __syncthreads();   // S4

    // -------- Phase E: out = x + cscale * (xn_e @ C_e)  (warp e) ------------
    {
        const int e = warp;
        ull acc[8][2];                       // [token-pair][col 2lane / 2lane+1]
        #pragma unroll
        for (int p = 0; p < 8; p++) { acc[p][0] = 0ull; acc[p][1] = 0ull; }
        const float* Cb = &gC[e][0][2 * lane];
        const ulonglong2* f2 = reinterpret_cast<const ulonglong2*>(&sm.fT[e * SS][0]);
        #pragma unroll 2
        for (int s = 0; s < SS; s++) {
            float2 cw = *reinterpret_cast<const float2*>(Cb + (long)s * SS);
            ull c0 = pk(cw.x, cw.x), c1 = pk(cw.y, cw.y);
            ulonglong2 fA = f2[s * 5 + 0];   // tokens 0..3
            ulonglong2 fB = f2[s * 5 + 1];   // tokens 4..7
            ulonglong2 fC = f2[s * 5 + 2];   // tokens 8..11
            ulonglong2 fD = f2[s * 5 + 3];   // tokens 12..15
            ffma2(acc[0][0], fA.x, c0); ffma2(acc[0][1], fA.x, c1);
            ffma2(acc[1][0], fA.y, c0); ffma2(acc[1][1], fA.y, c1);
            ffma2(acc[2][0], fB.x, c0); ffma2(acc[2][1], fB.x, c1);
            ffma2(acc[3][0], fB.y, c0); ffma2(acc[3][1], fB.y, c1);
            ffma2(acc[4][0], fC.x, c0); ffma2(acc[4][1], fC.x, c1);
            ffma2(acc[5][0], fC.y, c0); ffma2(acc[5][1], fC.y, c1);
            ffma2(acc[6][0], fD.x, c0); ffma2(acc[6][1], fD.x, c1);
            ffma2(acc[7][0], fD.y, c0); ffma2(acc[7][1], fD.y, c1);
        }
        const float* xb = x + g0 * DD + e * SS + 2 * lane;
        float* ob = out + g0 * DD + e * SS + 2 * lane;
        #pragma unroll
        for (int p = 0; p < 8; p++) {
            float a0lo, a0hi, a1lo, a1hi;
            upk(acc[p][0], a0lo, a0hi);
            upk(acc[p][1], a1lo, a1hi);
            const int t0 = 2 * p, t1 = 2 * p + 1;
            float cs0 = sm.fused_s[t0] * sm.mask_s[t0][e] * sm.gscale[e][t0];
            float cs1 = sm.fused_s[t1] * sm.mask_s[t1][e] * sm.gscale[e][t1];
            float2 xv0 = *reinterpret_cast<const float2*>(xb + (long)t0 * DD);
            float2 xv1 = *reinterpret_cast<const float2*>(xb + (long)t1 * DD);
            float2 o0, o1;
            o0.x = xv0.x + cs0 * a0lo; o0.y = xv0.y + cs0 * a1lo;
            o1.x = xv1.x + cs1 * a0hi; o1.y = xv1.y + cs1 * a1hi;
            *reinterpret_cast<float2*>(ob + (long)t0 * DD) = o0;
            *reinterpret_cast<float2*>(ob + (long)t1 * DD) = o1;
        }
    }
}

extern "C" void kernel_launch(void* const* d_in, const int* in_sizes, int n_in,
                              void* d_out, int out_size)
{
    (void)in_sizes; (void)n_in; (void)out_size;
    const float* x            = (const float*)d_in[0];
    const float* fingerprints = (const float*)d_in[1];
    const float* ln_gamma     = (const float*)d_in[2];
    const float* ln_beta      = (const float*)d_in[3];
    const float* w1           = (const float*)d_in[4];
    const float* b1           = (const float*)d_in[5];
    const float* w2           = (const float*)d_in[6];
    const float* b2           = (const float*)d_in[7];
    const float* alpha        = (const float*)d_in[8];
    const float* wv           = (const float*)d_in[9];
    const float* penta        = (const float*)d_in[10];
    const float* betas        = (const float*)d_in[11];
    const float* wout         = (const float*)d_in[12];
    const float* pos_embed    = (const float*)d_in[13];
    const float* temperature  = (const float*)d_in[14];
    float* out = (float*)d_out;

    precomp_scalars_kernel<<<EE, 256>>>(wv, penta, betas, alpha, pos_embed);
    precomp_C_kernel<<<EE * 16, 256>>>(wv, wout);

    cudaFuncSetAttribute(cantor_moe_kernel,
                         cudaFuncAttributeMaxDynamicSharedMemorySize,
                         (int)sizeof(Smem));

    dim3 grid(NTOK / TOK);
    cantor_moe_kernel<<<grid, THREADS, sizeof(Smem)>>>(
        x, fingerprints, ln_gamma, ln_beta, w1, b1, w2, b2,
        temperature, out);
}

// round 11
// speedup vs baseline: 1.3737x; 1.1089x over previous
#include <cuda_runtime.h>
#include <math.h>

// Problem constants
#define BB   8
#define PP   2048
#define DD   1024
#define EE   16
#define SS   64
#define DKK  128
#define HH   16
#define NTOK (BB*PP)          // 16384
#define TOK  16               // tokens per CTA
#define TOKP 20               // padded row: 80B -> token pairs 16B aligned
#define THREADS 512

typedef unsigned long long ull;

__device__ __forceinline__ float sigmoidf_(float v) { return 1.0f / (1.0f + expf(-v)); }

// packed f32x2 helpers (sm_100+)
__device__ __forceinline__ ull pk(float lo, float hi) {
    ull r; asm("mov.b64 %0,{%1,%2};" : "=l"(r) : "f"(lo), "f"(hi)); return r;
}
__device__ __forceinline__ void upk(ull v, float& lo, float& hi) {
    asm("mov.b64 {%0,%1},%2;" : "=f"(lo), "=f"(hi) : "l"(v));
}
__device__ __forceinline__ void ffma2(ull& acc, ull a, ull b) {
    asm("fma.rn.f32x2 %0,%1,%2,%0;" : "+l"(acc) : "l"(a), "l"(b));
}
__device__ __forceinline__ ull add2(ull a, ull b) {
    ull r; asm("add.rn.f32x2 %0,%1,%2;" : "=l"(r) : "l"(a), "l"(b)); return r;
}

// ---- precomputed per-expert constants (device globals: no allocation) ------
__device__ __align__(16) float gC[EE][SS][SS];   // C_e = wv_e @ wout_e (64x64)
__device__ __align__(16) float gQ[EE][SS];       // q_e = wv_e @ dbar_e
__device__ float gWE[EE];          // pos_w * beta_w
__device__ float gAW[EE];          // sigmoid(alpha)

// ==================== merged pre-kernel =====================================
// grid = 272, 256 threads.
//   bid < 256 : C tile (e = bid>>4, 4 rows of gC per CTA, 1 elem/thread)
//   bid >= 256: per-expert scalars + gQ for e = bid-256
__global__ void precomp_kernel(
    const float* __restrict__ wv,
    const float* __restrict__ wout,
    const float* __restrict__ penta,
    const float* __restrict__ betas,
    const float* __restrict__ alpha,
    const float* __restrict__ pos_embed)
{
    const int tid = threadIdx.x;
    const int warp = tid >> 5, lane = tid & 31;

    if (blockIdx.x < 256) {
        const int e = blockIdx.x >> 4;
        const int g = blockIdx.x & 15;
        const int s = g * 4 + (tid >> 6);         // 4 rows per CTA
        const int c = tid & 63;                   // col (warp-coalesced)
        const float* wvp = wv + ((long)e * SS + s) * DKK;
        const float* wop = wout + (long)e * DKK * SS + c;
        float acc = 0.0f;
        #pragma unroll 8
        for (int d = 0; d < DKK; d++)
            acc = fmaf(wvp[d], wop[(long)d * SS], acc);
        gC[e][s][c] = acc;
        return;
    }

    // -------------------- scalars for expert e -----------------------------
    const int e = blockIdx.x - 256;
    __shared__ float pinv[5];
    __shared__ __align__(16) float dbar[DKK];

    if (warp < 5) {
        float4 p = reinterpret_cast<const float4*>(penta + (long)(e * 5 + warp) * DKK)[lane];
        float sq = p.x * p.x + p.y * p.y + p.z * p.z + p.w * p.w;
        #pragma unroll
        for (int o = 16; o; o >>= 1) sq += __shfl_xor_sync(0xffffffffu, sq, o);
        if (lane == 0) pinv[warp] = rsqrtf(sq) * 0.2f;
    }
    if (warp == 6) {
        float4 pv = reinterpret_cast<const float4*>(pos_embed)[e * 32 + lane];
        float s = pv.x + pv.y + pv.z + pv.w;
        #pragma unroll
        for (int o = 16; o; o >>= 1) s += __shfl_xor_sync(0xffffffffu, s, o);
        if (lane == 0) {
            float pos_w = sigmoidf_(s * (1.0f / 128.0f));
            const int offs[4] = {-2, -1, 1, 2};
            float nv = 0.0f, bs = 0.0f;
            #pragma unroll
            for (int j = 0; j < 4; j++) {
                int nb = e + offs[j];
                if (nb >= 0 && nb < EE) { nv += 1.0f; bs += sigmoidf_(betas[e * 4 + j]); }
            }
            gWE[e] = pos_w * (1.0f + bs / nv);
            gAW[e] = sigmoidf_(alpha[e]);
        }
    }
    __syncthreads();
    if (tid < DKK) {
        float a = 0.0f;
        #pragma unroll
        for (int v = 0; v < 5; v++)
            a = fmaf(penta[(long)(e * 5 + v) * DKK + tid], pinv[v], a);
        dbar[tid] = a;
    }
    __syncthreads();
    // gQ: warp w handles rows w*8 .. w*8+7; lane-parallel over d (float4)
    {
        float4 db4 = reinterpret_cast<const float4*>(dbar)[lane];
        #pragma unroll
        for (int k = 0; k < 8; k++) {
            const int row = warp * 8 + k;
            float4 w4 = reinterpret_cast<const float4*>(
                            wv + ((long)e * SS + row) * DKK)[lane];
            float d = w4.x * db4.x + w4.y * db4.y + w4.z * db4.z + w4.w * db4.w;
            #pragma unroll
            for (int o = 16; o; o >>= 1) d += __shfl_xor_sync(0xffffffffu, d, o);
            if (lane == 0) gQ[e][row] = d;
        }
    }
}

// ============================ main kernel ===================================
struct __align__(16) Smem {
    float fT[DD][TOKP];         // 81920 B : xn, [channel][token], pairs 16B-aligned
    ull   h2[EE][TOK][9];       // 18432 B : gate hidden, j-pairs, row padded to 9 ull
    float Vdbraw[TOK][EE];      // xn_e . q_e  (pre-gscale)
    float gscale[EE][TOK];
    float mask_s[TOK][EE];
    float mw_s[TOK][EE];
    float den_s[TOK];
    float fused_s[TOK];
    float mean_s[TOK];
    float rstd_s[TOK];
};

__global__ __launch_bounds__(THREADS, 2)
void cantor_moe_kernel(
    const float* __restrict__ x,
    const float* __restrict__ fingerprints,
    const float* __restrict__ ln_gamma,
    const float* __restrict__ ln_beta,
    const float* __restrict__ w1,
    const float* __restrict__ b1,
    const float* __restrict__ w2,
    const float* __restrict__ b2,
    const float* __restrict__ temperature,
    float* __restrict__ out)
{
    extern __shared__ unsigned char smem_raw[];
    Smem& sm = *reinterpret_cast<Smem*>(smem_raw);

    const int tid  = threadIdx.x;
    const int warp = tid >> 5;
    const int lane = tid & 31;
    const long g0  = (long)blockIdx.x * TOK;

    // ---------------- LN pass 1: stats (warp t, vectorized) -----------------
    {
        const int t = warp;
        const long g = g0 + t;
        const float4* xr = reinterpret_cast<const float4*>(x + g * DD);
        float s = 0.0f, sq = 0.0f;
        #pragma unroll
        for (int i = 0; i < 8; i++) {
            float4 v = xr[i * 32 + lane];
            s  += v.x + v.y + v.z + v.w;
            sq += v.x * v.x + v.y * v.y + v.z * v.z + v.w * v.w;
        }
        #pragma unroll
        for (int o = 16; o; o >>= 1) {
            s  += __shfl_xor_sync(0xffffffffu, s,  o);
            sq += __shfl_xor_sync(0xffffffffu, sq, o);
        }
        if (lane == 0) {
            float mean = s * (1.0f / DD);
            sm.mean_s[t] = mean;
            sm.rstd_s[t] = rsqrtf(sq * (1.0f / DD) - mean * mean + 1e-5f);
        }
    }
    __syncthreads();   // S0: stats ready

    // ---------------- LN pass 2: transpose store, STS.128 -------------------
    {
        #pragma unroll
        for (int it = 0; it < 8; it++) {
            const int task = it * 16 + warp;
            const int cb = task >> 2, tq = task & 3;
            const int c = cb * 32 + lane;
            const float gm = ln_gamma[c];
            const float bt = ln_beta[c];
            float4 o;
            {
                const int t0 = tq * 4;
                float m0 = sm.mean_s[t0 + 0], r0 = sm.rstd_s[t0 + 0];
                float m1 = sm.mean_s[t0 + 1], r1 = sm.rstd_s[t0 + 1];
                float m2 = sm.mean_s[t0 + 2], r2 = sm.rstd_s[t0 + 2];
                float m3 = sm.mean_s[t0 + 3], r3 = sm.rstd_s[t0 + 3];
                float x0 = x[(g0 + t0 + 0) * DD + c];
                float x1 = x[(g0 + t0 + 1) * DD + c];
                float x2 = x[(g0 + t0 + 2) * DD + c];
                float x3 = x[(g0 + t0 + 3) * DD + c];
                o.x = (x0 - m0) * r0 * gm + bt;
                o.y = (x1 - m1) * r1 * gm + bt;
                o.z = (x2 - m2) * r2 * gm + bt;
                o.w = (x3 - m3) * r3 * gm + bt;
            }
            *reinterpret_cast<float4*>(&sm.fT[c][tq * 4]) = o;
        }
    }
    __syncthreads();   // S1: fT(xn) ready

    // -------- Phase B: tid<256 gate hidden | tid>=256 masks + Vdbraw --------
    if (tid < 256) {
        const int e  = tid >> 4;
        const int jg = (tid >> 2) & 3;
        const int tq = tid & 3;
        ull acc[4][2];
        #pragma unroll
        for (int t = 0; t < 4; t++) { acc[t][0] = 0ull; acc[t][1] = 0ull; }
        const ulonglong2* f2 = reinterpret_cast<const ulonglong2*>(&sm.fT[e * SS][0]);
        const float* w1b = w1 + (long)e * SS * HH + jg * 4;
        #pragma unroll 4
        for (int s = 0; s < SS; s++) {
            ulonglong2 fq = f2[s * 5 + tq];              // tokens 4tq..4tq+3
            float f0, f1, f2v, f3;
            upk(fq.x, f0, f1); upk(fq.y, f2v, f3);
            ulonglong2 w12 = *reinterpret_cast<const ulonglong2*>(w1b + (long)s * HH);
            ull fd0 = pk(f0, f0), fd1 = pk(f1, f1), fd2 = pk(f2v, f2v), fd3 = pk(f3, f3);
            ffma2(acc[0][0], fd0, w12.x); ffma2(acc[0][1], fd0, w12.y);
            ffma2(acc[1][0], fd1, w12.x); ffma2(acc[1][1], fd1, w12.y);
            ffma2(acc[2][0], fd2, w12.x); ffma2(acc[2][1], fd2, w12.y);
            ffma2(acc[3][0], fd3, w12.x); ffma2(acc[3][1], fd3, w12.y);
        }
        float2 b1a = *reinterpret_cast<const float2*>(b1 + e * HH + jg * 4);
        float2 b1b = *reinterpret_cast<const float2*>(b1 + e * HH + jg * 4 + 2);
        #pragma unroll
        for (int t = 0; t < 4; t++) {
            const int tok = tq * 4 + t;
            float h0, h1, h2v, h3;
            upk(acc[t][0], h0, h1);
            upk(acc[t][1], h2v, h3);
            h0 += b1a.x; h1 += b1a.y; h2v += b1b.x; h3 += b1b.y;
            h0  = 0.5f * h0  * (1.0f + erff(h0  * 0.70710678118654752f));
            h1  = 0.5f * h1  * (1.0f + erff(h1  * 0.70710678118654752f));
            h2v = 0.5f * h2v * (1.0f + erff(h2v * 0.70710678118654752f));
            h3  = 0.5f * h3  * (1.0f + erff(h3  * 0.70710678118654752f));
            sm.h2[e][tok][2 * jg + 0] = pk(h0, h1);
            sm.h2[e][tok][2 * jg + 1] = pk(h2v, h3);
        }
    } else {
        // masks / mw
        {
            const int qq = tid - 256;
            const int t = qq >> 4, e = qq & 15;
            const long g = g0 + t;
            float f = fingerprints[(int)(g & (PP - 1))];
            float fmin = fmaxf(0.0f, e * (1.0f / EE) - 0.03125f);
            float fmax = fminf(1.0f, (e + 1) * (1.0f / EE) + 0.03125f);
            float mval = (f >= fmin && f < fmax) ? 1.0f : 0.0f;
            sm.mask_s[t][e] = mval;
            sm.mw_s[t][e]   = mval * gWE[e];
        }
        // Vdbraw: warp w (8..15) handles experts w-8 and w
        #pragma unroll
        for (int ee = 0; ee < 2; ee++) {
            const int e = (warp - 8) + ee * 8;
            ull acc[8];
            #pragma unroll
            for (int p = 0; p < 8; p++) acc[p] = 0ull;
            #pragma unroll
            for (int si = 0; si < 2; si++) {
                const int s = lane + si * 32;
                float qv = gQ[e][s];
                ull qd = pk(qv, qv);
                const ull* fp = reinterpret_cast<const ull*>(&sm.fT[e * SS + s][0]);
                #pragma unroll
                for (int p = 0; p < 8; p++) ffma2(acc[p], fp[p], qd);
            }
            #pragma unroll
            for (int o = 16; o; o >>= 1)
                #pragma unroll
                for (int p = 0; p < 8; p++)
                    acc[p] = add2(acc[p], __shfl_xor_sync(0xffffffffu, acc[p], o));
            if (lane == 0) {
                #pragma unroll
                for (int p = 0; p < 8; p++) {
                    float lo, hi; upk(acc[p], lo, hi);
                    sm.Vdbraw[2 * p + 0][e] = lo;
                    sm.Vdbraw[2 * p + 1][e] = hi;
                }
            }
        }
    }
    __syncthreads();   // S2: h2, mask, mw, Vdbraw ready

    // -------- Phase C: gscale (tid<256) + den -------------------------------
    if (tid < TOK * EE) {
        const int e = tid >> 4, t = tid & 15;
        ull acc = 0ull;
        const ull* hp = &sm.h2[e][t][0];
        const ull* w2p = reinterpret_cast<const ull*>(w2 + e * HH);
        #pragma unroll
        for (int jp = 0; jp < 8; jp++) ffma2(acc, hp[jp], w2p[jp]);
        float lo, hi; upk(acc, lo, hi);
        float gate = sigmoidf_(lo + hi + b2[e]);
        float aw = gAW[e];
        sm.gscale[e][t] = gate * aw + (1.0f - aw);
    } else if (tid < TOK * EE + TOK) {
        const int t = tid - TOK * EE;
        float s = 0.0f;
        #pragma unroll
        for (int e = 0; e < EE; e++) s += sm.mw_s[t][e];
        sm.den_s[t] = fmaxf(s, 1e-6f);
    }
    __syncthreads();   // S3

    // -------- Phase D: fused scalar (gscale folded in) ----------------------
    if (tid < TOK) {
        const int t = tid;
        float s = 0.0f;
        #pragma unroll
        for (int e = 0; e < EE; e++)
            s += sm.mw_s[t][e] * sm.gscale[e][t] * sm.Vdbraw[t][e];
        sm.fused_s[t] = s / (sm.den_s[t] * fabsf(temperature[0]));
    }
    __syncthreads();   // S4

    // -------- Phase E: out = x + cscale * (xn_e @ C_e)  (warp e) ------------
    {
        const int e = warp;
        ull acc[8][2];                       // [token-pair][col 2lane / 2lane+1]
        #pragma unroll
        for (int p = 0; p < 8; p++) { acc[p][0] = 0ull; acc[p][1] = 0ull; }
        const float* Cb = &gC[e][0][2 * lane];
        const ulonglong2* f2 = reinterpret_cast<const ulonglong2*>(&sm.fT[e * SS][0]);
        #pragma unroll 2
        for (int s = 0; s < SS; s++) {
            float2 cw = *reinterpret_cast<const float2*>(Cb + (long)s * SS);
            ull c0 = pk(cw.x, cw.x), c1 = pk(cw.y, cw.y);
            ulonglong2 fA = f2[s * 5 + 0];   // tokens 0..3
            ulonglong2 fB = f2[s * 5 + 1];   // tokens 4..7
            ulonglong2 fC = f2[s * 5 + 2];   // tokens 8..11
            ulonglong2 fD = f2[s * 5 + 3];   // tokens 12..15
            ffma2(acc[0][0], fA.x, c0); ffma2(acc[0][1], fA.x, c1);
            ffma2(acc[1][0], fA.y, c0); ffma2(acc[1][1], fA.y, c1);
            ffma2(acc[2][0], fB.x, c0); ffma2(acc[2][1], fB.x, c1);
            ffma2(acc[3][0], fB.y, c0); ffma2(acc[3][1], fB.y, c1);
            ffma2(acc[4][0], fC.x, c0); ffma2(acc[4][1], fC.x, c1);
            ffma2(acc[5][0], fC.y, c0); ffma2(acc[5][1], fC.y, c1);
            ffma2(acc[6][0], fD.x, c0); ffma2(acc[6][1], fD.x, c1);
            ffma2(acc[7][0], fD.y, c0); ffma2(acc[7][1], fD.y, c1);
        }
        const float* xb = x + g0 * DD + e * SS + 2 * lane;
        float* ob = out + g0 * DD + e * SS + 2 * lane;
        #pragma unroll
        for (int p = 0; p < 8; p++) {
            float a0lo, a0hi, a1lo, a1hi;
            upk(acc[p][0], a0lo, a0hi);
            upk(acc[p][1], a1lo, a1hi);
            const int t0 = 2 * p, t1 = 2 * p + 1;
            float cs0 = sm.fused_s[t0] * sm.mask_s[t0][e] * sm.gscale[e][t0];
            float cs1 = sm.fused_s[t1] * sm.mask_s[t1][e] * sm.gscale[e][t1];
            float2 xv0 = *reinterpret_cast<const float2*>(xb + (long)t0 * DD);
            float2 xv1 = *reinterpret_cast<const float2*>(xb + (long)t1 * DD);
            float2 o0, o1;
            o0.x = xv0.x + cs0 * a0lo; o0.y = xv0.y + cs0 * a1lo;
            o1.x = xv1.x + cs1 * a0hi; o1.y = xv1.y + cs1 * a1hi;
            *reinterpret_cast<float2*>(ob + (long)t0 * DD) = o0;
            *reinterpret_cast<float2*>(ob + (long)t1 * DD) = o1;
        }
    }
}

extern "C" void kernel_launch(void* const* d_in, const int* in_sizes, int n_in,
                              void* d_out, int out_size)
{
    (void)in_sizes; (void)n_in; (void)out_size;
    const float* x            = (const float*)d_in[0];
    const float* fingerprints = (const float*)d_in[1];
    const float* ln_gamma     = (const float*)d_in[2];
    const float* ln_beta      = (const float*)d_in[3];
    const float* w1           = (const float*)d_in[4];
    const float* b1           = (const float*)d_in[5];
    const float* w2           = (const float*)d_in[6];
    const float* b2           = (const float*)d_in[7];
    const float* alpha        = (const float*)d_in[8];
    const float* wv           = (const float*)d_in[9];
    const float* penta        = (const float*)d_in[10];
    const float* betas        = (const float*)d_in[11];
    const float* wout         = (const float*)d_in[12];
    const float* pos_embed    = (const float*)d_in[13];
    const float* temperature  = (const float*)d_in[14];
    float* out = (float*)d_out;

    precomp_kernel<<<272, 256>>>(wv, wout, penta, betas, alpha, pos_embed);

    cudaFuncSetAttribute(cantor_moe_kernel,
                         cudaFuncAttributeMaxDynamicSharedMemorySize,
                         (int)sizeof(Smem));

    dim3 grid(NTOK / TOK);
    cantor_moe_kernel<<<grid, THREADS, sizeof(Smem)>>>(
        x, fingerprints, ln_gamma, ln_beta, w1, b1, w2, b2,
        temperature, out);
}